// round 2
// baseline (speedup 1.0000x reference)
#include <cuda_runtime.h>
#include <math.h>

#define NQ    128
#define ED    256
#define DFFD  512
#define CAMSN 6
#define TSTEP 2
#define CFCH  256
#define HGT   64
#define WID   160
#define PLANE (HGT*WID)      /* 10240 */
#define NPTS  150

// ---------------- device scratch (no allocations allowed) ----------------
__device__ float g_q    [NQ*ED];
__device__ float g_h    [NQ*DFFD];
__device__ float g_agg  [NQ*ED];
__device__ float g_mem  [NQ*ED];
__device__ float g_qkv  [NQ*3*ED];
__device__ float g_attno[NQ*ED];
__device__ float g_tmp  [NQ*ED];
__device__ float g_tp   [NQ*11];

// ---------------- simple copy ----------------
__global__ void copy_kernel(const float* __restrict__ src, float* __restrict__ dst, int n) {
    int i = blockIdx.x * blockDim.x + threadIdx.x;
    if (i < n) dst[i] = src[i];
}

// ---------------- tiled fp32 GEMM: C[M,N] = act(A @ W^T + bias) ----------------
// A: [M,K] row-major (source switches to A2 for output cols >= 256 when A2 != nullptr)
// W: [N,K] row-major, bias: [N]
// BM=32, BN=64, BK=16, 256 threads, each thread computes 2x4 outputs.
#define GBM 32
#define GBN 64
#define GBK 16

template <int ACT>
__global__ void gemm_kernel(const float* __restrict__ A, const float* __restrict__ A2,
                            const float* __restrict__ W, const float* __restrict__ Bb,
                            float* __restrict__ C, int M, int N, int K)
{
    __shared__ float As[GBK][GBM + 4];   // [16][36]
    __shared__ float Ws[GBK][GBN + 4];   // [16][68]

    int m0 = blockIdx.x * GBM;
    int n0 = blockIdx.y * GBN;
    const float* Asrc = (A2 != nullptr && n0 >= 256) ? A2 : A;

    int t  = threadIdx.x;
    int tx = t & 15;        // 0..15 -> 4 cols each
    int ty = t >> 4;        // 0..15 -> 2 rows each

    float acc[2][4] = {{0.f,0.f,0.f,0.f},{0.f,0.f,0.f,0.f}};

    for (int k0 = 0; k0 < K; k0 += GBK) {
        if (t < 128) {
            int r = t >> 2, kq = t & 3;
            float4 v = *(const float4*)&Asrc[(m0 + r) * K + k0 + kq * 4];
            As[kq*4+0][r] = v.x; As[kq*4+1][r] = v.y;
            As[kq*4+2][r] = v.z; As[kq*4+3][r] = v.w;
        }
        {
            int r = t >> 2, kq = t & 3;
            float4 v = *(const float4*)&W[(n0 + r) * K + k0 + kq * 4];
            Ws[kq*4+0][r] = v.x; Ws[kq*4+1][r] = v.y;
            Ws[kq*4+2][r] = v.z; Ws[kq*4+3][r] = v.w;
        }
        __syncthreads();
        #pragma unroll
        for (int k = 0; k < GBK; k++) {
            float a0 = As[k][ty*2+0];
            float a1 = As[k][ty*2+1];
            float4 w = *(const float4*)&Ws[k][tx*4];
            acc[0][0] = fmaf(a0, w.x, acc[0][0]);
            acc[0][1] = fmaf(a0, w.y, acc[0][1]);
            acc[0][2] = fmaf(a0, w.z, acc[0][2]);
            acc[0][3] = fmaf(a0, w.w, acc[0][3]);
            acc[1][0] = fmaf(a1, w.x, acc[1][0]);
            acc[1][1] = fmaf(a1, w.y, acc[1][1]);
            acc[1][2] = fmaf(a1, w.z, acc[1][2]);
            acc[1][3] = fmaf(a1, w.w, acc[1][3]);
        }
        __syncthreads();
    }

    int col = n0 + tx * 4;
    float4 bv = *(const float4*)&Bb[col];
    #pragma unroll
    for (int i = 0; i < 2; i++) {
        int row = m0 + ty * 2 + i;
        float4 r;
        r.x = acc[i][0] + bv.x;
        r.y = acc[i][1] + bv.y;
        r.z = acc[i][2] + bv.z;
        r.w = acc[i][3] + bv.w;
        if (ACT) {
            r.x = fmaxf(r.x, 0.f); r.y = fmaxf(r.y, 0.f);
            r.z = fmaxf(r.z, 0.f); r.w = fmaxf(r.w, 0.f);
        }
        *(float4*)&C[row * N + col] = r;
    }
}

// ---------------- traj head second layer: tp[m,k] = h[m,:] @ w2[k,:] + b2[k] ----------------
// grid 128 (query), 352 threads = 11 warps (one per output col). Writes g_tp and the output slab.
__global__ void traj2_kernel(const float* __restrict__ h, const float* __restrict__ w2,
                             const float* __restrict__ b2, float* __restrict__ tp,
                             float* __restrict__ outp)
{
    int m = blockIdx.x;
    int t = threadIdx.x;
    int k = t >> 5, lane = t & 31;
    float s = 0.f;
    for (int d = lane; d < 512; d += 32)
        s = fmaf(h[m * 512 + d], w2[k * 512 + d], s);
    for (int o = 16; o; o >>= 1) s += __shfl_xor_sync(0xffffffffu, s, o);
    if (lane == 0) {
        float v = s + b2[k];
        tp[m * 11 + k]   = v;
        outp[m * 11 + k] = v;
    }
}

// ---------------- projection + bilinear sampling + accumulate ----------------
// grid 128 (one block per query), 256 threads (8 warps).
__global__ void sample_kernel(const float* __restrict__ tp, const float* __restrict__ feat,
                              const float* __restrict__ calib, const float* __restrict__ ego,
                              float* __restrict__ agg)
{
    __shared__ float s_tp[11];
    __shared__ int   s_off[NPTS];
    __shared__ float s_wx[NPTS];
    __shared__ float s_wy[NPTS];
    __shared__ float s_acc[ED];

    int m = blockIdx.x;
    int t = threadIdx.x;
    int lane = t & 31, w = t >> 5;

    if (t < 11)  s_tp[t] = tp[m * 11 + t];
    s_acc[t] = 0.f;
    __syncthreads();

    float facc[8] = {0.f,0.f,0.f,0.f,0.f,0.f,0.f,0.f};

    for (int tt = 0; tt < TSTEP; tt++) {
        float dt   = ego[tt * 4 + 3] - ego[1 * 4 + 3];
        float ex   = ego[tt * 4 + 0];
        float ey   = ego[tt * 4 + 1];
        float eyaw = ego[tt * 4 + 2];
        float ce = cosf(eyaw), se = sinf(eyaw);

        for (int ci = 0; ci < CAMSN; ci++) {
            // Phase A: threads 0..149 compute projection params for this (cam, t)
            if (t < NPTS) {
                int face = t / 25, idx = t % 25, dim = face >> 1;
                float sign = (face & 1) ? 1.0f : -1.0f;
                float a = -1.0f + 0.5f * (float)(idx / 5);
                float b = -1.0f + 0.5f * (float)(idx % 5);
                float ux, uy, uz;
                if (dim == 0)      { ux = sign; uy = a;    uz = b; }
                else if (dim == 1) { ux = a;    uy = sign; uz = b; }
                else               { ux = a;    uy = b;    uz = sign; }

                float lx = ux * s_tp[8], ly = uy * s_tp[9], lz = uz * s_tp[10];
                float yaw = s_tp[7];
                float cyw = cosf(yaw), syw = sinf(yaw);
                float rx = lx * cyw - ly * syw;
                float ry = lx * syw + ly * cyw;
                float cx = s_tp[0] + s_tp[3] * dt + 0.5f * s_tp[5] * dt * dt;
                float cy = s_tp[1] + s_tp[4] * dt + 0.5f * s_tp[6] * dt * dt;
                float wx = rx + cx, wy = ry + cy, wz = lz + s_tp[2];
                float pxr = wx - ex, pyr = wy - ey;
                float gx =  pxr * ce + pyr * se;
                float gy = -pxr * se + pyr * ce;

                const float* cal = calib + ci * 8;
                float fx = cal[0], fy = cal[1], cx0 = cal[2], cy0 = cal[3];
                float tx = cal[4], tyc = cal[5], tz = cal[6], cyaw = cal[7];
                float px = gx - tx, py = gy - tyc, pz = wz - tz;
                float cc = cosf(cyaw), sc = sinf(cyaw);
                float fwd  =  px * cc + py * sc;
                float left = -px * sc + py * cc;
                float zc = fwd, xc = -left, yc = -pz;
                float zs = fmaxf(zc, 0.1f);
                float u = fx * xc / zs + cx0;
                float v = fy * yc / zs + cy0;
                bool valid = (zc > 0.1f) && (u >= 0.f) && (u < 1.f) && (v >= 0.f) && (v < 1.f);
                if (valid) {
                    float pxi = u * 159.0f;
                    float pyi = v * 63.0f;
                    float x0f = floorf(pxi), y0f = floorf(pyi);
                    int x0 = (int)x0f, y0 = (int)y0f;
                    s_off[t] = y0 * WID + x0;
                    s_wx[t]  = pxi - x0f;
                    s_wy[t]  = pyi - y0f;
                } else {
                    s_off[t] = -1;
                }
            }
            __syncthreads();

            // Phase B: warps sample points; lane = channel (c = cc*32 + lane)
            const float* fbase = feat + ((size_t)(ci * TSTEP + tt)) * (size_t)(CFCH * PLANE);
            for (int p = w; p < NPTS; p += 8) {
                int off = s_off[p];
                if (off < 0) continue;
                float wxk = s_wx[p], wyk = s_wy[p];
                float w00 = (1.f - wxk) * (1.f - wyk);
                float w01 = wxk * (1.f - wyk);
                float w10 = (1.f - wxk) * wyk;
                float w11 = wxk * wyk;
                const float* fp = fbase + off + lane * PLANE;
                #pragma unroll
                for (int cc = 0; cc < 8; cc++) {
                    const float* q0 = fp + cc * (32 * PLANE);
                    float f00 = q0[0];
                    float f01 = q0[1];
                    float f10 = q0[WID];
                    float f11 = q0[WID + 1];
                    facc[cc] += f00 * w00 + f01 * w01 + f10 * w10 + f11 * w11;
                }
            }
            __syncthreads();
        }
    }

    #pragma unroll
    for (int cc = 0; cc < 8; cc++)
        atomicAdd(&s_acc[cc * 32 + lane], facc[cc]);
    __syncthreads();
    agg[m * ED + t] = s_acc[t] * (1.0f / 1800.0f);
}

// ---------------- multi-head attention core ----------------
// qkv: [128][768] = [q | k | v], 8 heads x d=32. grid (8 heads, 4 q-chunks of 32), 256 threads.
__global__ void attn_kernel(const float* __restrict__ qkv, float* __restrict__ outb)
{
    __shared__ float Ks[128 * 33];
    __shared__ float Vs[128 * 33];
    __shared__ float Qs[32 * 33];
    __shared__ float Ps[8 * 128];

    int hh = blockIdx.x;
    int qbase = blockIdx.y * 32;
    int t = threadIdx.x, lane = t & 31, w = t >> 5;

    for (int idx = t; idx < 4096; idx += 256) {
        int j = idx >> 5, d = idx & 31;
        Ks[j * 33 + d] = qkv[j * 768 + 256 + hh * 32 + d];
        Vs[j * 33 + d] = qkv[j * 768 + 512 + hh * 32 + d];
    }
    for (int idx = t; idx < 1024; idx += 256) {
        int il = idx >> 5, d = idx & 31;
        Qs[il * 33 + d] = qkv[(qbase + il) * 768 + hh * 32 + d];
    }
    __syncthreads();

    for (int r = 0; r < 4; r++) {
        int il = w * 4 + r;
        float s[4];
        #pragma unroll
        for (int jj = 0; jj < 4; jj++) {
            int j = jj * 32 + lane;
            float a = 0.f;
            #pragma unroll
            for (int d = 0; d < 32; d++)
                a = fmaf(Qs[il * 33 + d], Ks[j * 33 + d], a);
            s[jj] = a * 0.17677669529663687f;   // 1/sqrt(32)
        }
        float mx = fmaxf(fmaxf(s[0], s[1]), fmaxf(s[2], s[3]));
        for (int o = 16; o; o >>= 1) mx = fmaxf(mx, __shfl_xor_sync(0xffffffffu, mx, o));
        float ssum = 0.f;
        #pragma unroll
        for (int jj = 0; jj < 4; jj++) { s[jj] = expf(s[jj] - mx); ssum += s[jj]; }
        for (int o = 16; o; o >>= 1) ssum += __shfl_xor_sync(0xffffffffu, ssum, o);
        #pragma unroll
        for (int jj = 0; jj < 4; jj++) Ps[w * 128 + jj * 32 + lane] = s[jj];
        __syncwarp();
        float ov = 0.f;
        for (int j = 0; j < 128; j++)
            ov = fmaf(Ps[w * 128 + j], Vs[j * 33 + lane], ov);
        outb[(qbase + il) * 256 + hh * 32 + lane] = ov / ssum;
        __syncwarp();
    }
}

// ---------------- residual add + LayerNorm (in-place on q) ----------------
// grid 128, 256 threads.
__global__ void resln_kernel(float* __restrict__ q, const float* __restrict__ add,
                             const float* __restrict__ g, const float* __restrict__ b)
{
    __shared__ float red[8];
    int i = blockIdx.x, t = threadIdx.x;
    float x = q[i * 256 + t] + add[i * 256 + t];

    float v = x;
    for (int o = 16; o; o >>= 1) v += __shfl_xor_sync(0xffffffffu, v, o);
    if ((t & 31) == 0) red[t >> 5] = v;
    __syncthreads();
    float total = 0.f;
    #pragma unroll
    for (int kk = 0; kk < 8; kk++) total += red[kk];
    float mean = total * (1.0f / 256.0f);
    float xm = x - mean;
    __syncthreads();

    float v2 = xm * xm;
    for (int o = 16; o; o >>= 1) v2 += __shfl_xor_sync(0xffffffffu, v2, o);
    if ((t & 31) == 0) red[t >> 5] = v2;
    __syncthreads();
    float tv = 0.f;
    #pragma unroll
    for (int kk = 0; kk < 8; kk++) tv += red[kk];
    float var = tv * (1.0f / 256.0f);

    q[i * 256 + t] = xm * rsqrtf(var + 1e-5f) * g[t] + b[t];
}

// ---------------- host orchestration ----------------
extern "C" void kernel_launch(void* const* d_in, const int* in_sizes, int n_in,
                              void* d_out, int out_size)
{
    const float* features = (const float*)d_in[0];
    const float* calib    = (const float*)d_in[1];
    const float* ego      = (const float*)d_in[2];
    const float* queries  = (const float*)d_in[3];
    // d_in[4] = query_pos (unused by reference)
    const float* tw1  = (const float*)d_in[5];
    const float* tb1  = (const float*)d_in[6];
    const float* tw2  = (const float*)d_in[7];
    const float* tb2  = (const float*)d_in[8];
    const float* fmw1 = (const float*)d_in[9];
    const float* fmb1 = (const float*)d_in[10];
    const float* fmw2 = (const float*)d_in[11];
    const float* fmb2 = (const float*)d_in[12];
    const float* saiw = (const float*)d_in[13];
    const float* saib = (const float*)d_in[14];
    const float* saow = (const float*)d_in[15];
    const float* saob = (const float*)d_in[16];
    const float* caiw = (const float*)d_in[17];
    const float* caib = (const float*)d_in[18];
    const float* caow = (const float*)d_in[19];
    const float* caob = (const float*)d_in[20];
    const float* l1w  = (const float*)d_in[21];
    const float* l1b  = (const float*)d_in[22];
    const float* l2w  = (const float*)d_in[23];
    const float* l2b  = (const float*)d_in[24];
    const float* n1g  = (const float*)d_in[25];
    const float* n1b  = (const float*)d_in[26];
    const float* n2g  = (const float*)d_in[27];
    const float* n2b  = (const float*)d_in[28];
    const float* n3g  = (const float*)d_in[29];
    const float* n3b  = (const float*)d_in[30];
    float* out = (float*)d_out;

    float *q, *h, *agg, *mem, *qkv, *attno, *tmp, *tp;
    cudaGetSymbolAddress((void**)&q,     g_q);
    cudaGetSymbolAddress((void**)&h,     g_h);
    cudaGetSymbolAddress((void**)&agg,   g_agg);
    cudaGetSymbolAddress((void**)&mem,   g_mem);
    cudaGetSymbolAddress((void**)&qkv,   g_qkv);
    cudaGetSymbolAddress((void**)&attno, g_attno);
    cudaGetSymbolAddress((void**)&tmp,   g_tmp);
    cudaGetSymbolAddress((void**)&tp,    g_tp);

    copy_kernel<<<(NQ * ED + 255) / 256, 256>>>(queries, q, NQ * ED);

    for (int li = 0; li < 6; li++) {
        // traj head
        gemm_kernel<1><<<dim3(4, 8), 256>>>(q, nullptr, tw1, tb1, h, 128, 512, 256);
        traj2_kernel<<<128, 352>>>(h, tw2, tb2, tp, out + li * 1408);

        // multi-camera deformable sampling
        sample_kernel<<<128, 256>>>(tp, features, calib, ego, agg);

        // feature MLP -> mem
        gemm_kernel<1><<<dim3(4, 8), 256>>>(agg, nullptr, fmw1, fmb1, h, 128, 512, 256);
        gemm_kernel<0><<<dim3(4, 4), 256>>>(h, nullptr, fmw2, fmb2, mem, 128, 256, 512);

        // self-attention
        gemm_kernel<0><<<dim3(4, 12), 256>>>(q, nullptr, saiw + li * 768 * 256, saib + li * 768,
                                             qkv, 128, 768, 256);
        attn_kernel<<<dim3(8, 4), 256>>>(qkv, attno);
        gemm_kernel<0><<<dim3(4, 4), 256>>>(attno, nullptr, saow + li * 256 * 256, saob + li * 256,
                                            tmp, 128, 256, 256);
        resln_kernel<<<128, 256>>>(q, tmp, n1g + li * 256, n1b + li * 256);

        // cross-attention (q from q; k,v from mem via A2 column switch)
        gemm_kernel<0><<<dim3(4, 12), 256>>>(q, mem, caiw + li * 768 * 256, caib + li * 768,
                                             qkv, 128, 768, 256);
        attn_kernel<<<dim3(8, 4), 256>>>(qkv, attno);
        gemm_kernel<0><<<dim3(4, 4), 256>>>(attno, nullptr, caow + li * 256 * 256, caob + li * 256,
                                            tmp, 128, 256, 256);
        resln_kernel<<<128, 256>>>(q, tmp, n2g + li * 256, n2b + li * 256);

        // FFN
        gemm_kernel<1><<<dim3(4, 8), 256>>>(q, nullptr, l1w + li * 512 * 256, l1b + li * 512,
                                            h, 128, 512, 256);
        gemm_kernel<0><<<dim3(4, 4), 256>>>(h, nullptr, l2w + li * 256 * 512, l2b + li * 256,
                                            tmp, 128, 256, 512);
        resln_kernel<<<128, 256>>>(q, tmp, n3g + li * 256, n3b + li * 256);
    }

    // final traj head
    gemm_kernel<1><<<dim3(4, 8), 256>>>(q, nullptr, tw1, tb1, h, 128, 512, 256);
    traj2_kernel<<<128, 352>>>(h, tw2, tb2, tp, out + 6 * 1408);
}

// round 3
// speedup vs baseline: 3.2584x; 3.2584x over previous
#include <cuda_runtime.h>
#include <math.h>

#define NQ    128
#define ED    256
#define DFFD  512
#define CAMSN 6
#define TSTEP 2
#define CFCH  256
#define HGT   64
#define WID   160
#define PLANE (HGT*WID)      /* 10240 */
#define NPTS  150
#define NTAPS (NPTS*CAMSN*TSTEP)  /* 1800 */

// ---------------- device scratch (no allocations allowed) ----------------
__device__ float g_q    [NQ*ED];
__device__ float g_h    [NQ*DFFD];
__device__ float g_agg  [NQ*ED];
__device__ float g_mem  [NQ*ED];
__device__ float g_qkv  [NQ*3*ED];
__device__ float g_attno[NQ*ED];
__device__ float g_tmp  [NQ*ED];
__device__ float g_tp   [NQ*11];
__device__ float g_featT[(size_t)CAMSN*TSTEP*PLANE*CFCH];  // 126 MB, pixel-major

// ---------------- simple copy ----------------
__global__ void copy_kernel(const float* __restrict__ src, float* __restrict__ dst, int n) {
    int i = blockIdx.x * blockDim.x + threadIdx.x;
    if (i < n) dst[i] = src[i];
}

// ---------------- feature transpose: [ct][C][pix] -> [ct][pix][C] ----------------
// block (32,8), grid (PLANE/32, CFCH/32, 12)
__global__ void transpose_kernel(const float* __restrict__ feat, float* __restrict__ featT)
{
    __shared__ float tile[32][33];
    int ct = blockIdx.z;
    int p0 = blockIdx.x * 32;
    int c0 = blockIdx.y * 32;
    const float* in  = feat  + (size_t)ct * CFCH * PLANE;
    float*       out = featT + (size_t)ct * CFCH * PLANE;
    int tx = threadIdx.x, ty = threadIdx.y;
    #pragma unroll
    for (int i = 0; i < 32; i += 8)
        tile[ty + i][tx] = in[(size_t)(c0 + ty + i) * PLANE + p0 + tx];
    __syncthreads();
    #pragma unroll
    for (int i = 0; i < 32; i += 8)
        out[(size_t)(p0 + ty + i) * CFCH + c0 + tx] = tile[tx][ty + i];
}

// ---------------- tiled fp32 GEMM: C[M,N] = act(A @ W^T + bias) ----------------
#define GBM 32
#define GBN 64
#define GBK 16

template <int ACT>
__global__ void gemm_kernel(const float* __restrict__ A, const float* __restrict__ A2,
                            const float* __restrict__ W, const float* __restrict__ Bb,
                            float* __restrict__ C, int M, int N, int K)
{
    __shared__ float As[GBK][GBM + 4];
    __shared__ float Ws[GBK][GBN + 4];

    int m0 = blockIdx.x * GBM;
    int n0 = blockIdx.y * GBN;
    const float* Asrc = (A2 != nullptr && n0 >= 256) ? A2 : A;

    int t  = threadIdx.x;
    int tx = t & 15;
    int ty = t >> 4;

    float acc[2][4] = {{0.f,0.f,0.f,0.f},{0.f,0.f,0.f,0.f}};

    for (int k0 = 0; k0 < K; k0 += GBK) {
        if (t < 128) {
            int r = t >> 2, kq = t & 3;
            float4 v = *(const float4*)&Asrc[(m0 + r) * K + k0 + kq * 4];
            As[kq*4+0][r] = v.x; As[kq*4+1][r] = v.y;
            As[kq*4+2][r] = v.z; As[kq*4+3][r] = v.w;
        }
        {
            int r = t >> 2, kq = t & 3;
            float4 v = *(const float4*)&W[(n0 + r) * K + k0 + kq * 4];
            Ws[kq*4+0][r] = v.x; Ws[kq*4+1][r] = v.y;
            Ws[kq*4+2][r] = v.z; Ws[kq*4+3][r] = v.w;
        }
        __syncthreads();
        #pragma unroll
        for (int k = 0; k < GBK; k++) {
            float a0 = As[k][ty*2+0];
            float a1 = As[k][ty*2+1];
            float4 w = *(const float4*)&Ws[k][tx*4];
            acc[0][0] = fmaf(a0, w.x, acc[0][0]);
            acc[0][1] = fmaf(a0, w.y, acc[0][1]);
            acc[0][2] = fmaf(a0, w.z, acc[0][2]);
            acc[0][3] = fmaf(a0, w.w, acc[0][3]);
            acc[1][0] = fmaf(a1, w.x, acc[1][0]);
            acc[1][1] = fmaf(a1, w.y, acc[1][1]);
            acc[1][2] = fmaf(a1, w.z, acc[1][2]);
            acc[1][3] = fmaf(a1, w.w, acc[1][3]);
        }
        __syncthreads();
    }

    int col = n0 + tx * 4;
    float4 bv = *(const float4*)&Bb[col];
    #pragma unroll
    for (int i = 0; i < 2; i++) {
        int row = m0 + ty * 2 + i;
        float4 r;
        r.x = acc[i][0] + bv.x;
        r.y = acc[i][1] + bv.y;
        r.z = acc[i][2] + bv.z;
        r.w = acc[i][3] + bv.w;
        if (ACT) {
            r.x = fmaxf(r.x, 0.f); r.y = fmaxf(r.y, 0.f);
            r.z = fmaxf(r.z, 0.f); r.w = fmaxf(r.w, 0.f);
        }
        *(float4*)&C[row * N + col] = r;
    }
}

// ---------------- traj head second layer ----------------
__global__ void traj2_kernel(const float* __restrict__ h, const float* __restrict__ w2,
                             const float* __restrict__ b2, float* __restrict__ tp,
                             float* __restrict__ outp)
{
    int m = blockIdx.x;
    int t = threadIdx.x;
    int k = t >> 5, lane = t & 31;
    float s = 0.f;
    for (int d = lane; d < 512; d += 32)
        s = fmaf(h[m * 512 + d], w2[k * 512 + d], s);
    for (int o = 16; o; o >>= 1) s += __shfl_xor_sync(0xffffffffu, s, o);
    if (lane == 0) {
        float v = s + b2[k];
        tp[m * 11 + k]   = v;
        outp[m * 11 + k] = v;
    }
}

// ---------------- projection + bilinear sampling over transposed features ----------------
// grid (NQ, 2), block 128. Thread = channel (chunk*128 + t).
__global__ void sample_kernel(const float* __restrict__ tp, const float* __restrict__ featT,
                              const float* __restrict__ calib, const float* __restrict__ ego,
                              float* __restrict__ agg)
{
    __shared__ float  s_tp[11];
    __shared__ int    s_row[NTAPS];
    __shared__ float4 s_w[NTAPS];

    int m = blockIdx.x;
    int chunk = blockIdx.y;
    int t = threadIdx.x;        // 0..127
    int c = chunk * 128 + t;

    if (t < 11) s_tp[t] = tp[m * 11 + t];
    __syncthreads();

    // Phase A: project all 1800 (tap = ctc*150 + pt, ctc = tt*6+ci)
    for (int idx = t; idx < NTAPS; idx += 128) {
        int pt  = idx % NPTS;
        int ctc = idx / NPTS;
        int ci  = ctc % CAMSN;
        int tt  = ctc / CAMSN;

        float dt   = ego[tt * 4 + 3] - ego[1 * 4 + 3];
        float ex   = ego[tt * 4 + 0];
        float ey   = ego[tt * 4 + 1];
        float eyaw = ego[tt * 4 + 2];
        float ce = cosf(eyaw), se = sinf(eyaw);

        int face = pt / 25, sub = pt % 25, dim = face >> 1;
        float sign = (face & 1) ? 1.0f : -1.0f;
        float a = -1.0f + 0.5f * (float)(sub / 5);
        float b = -1.0f + 0.5f * (float)(sub % 5);
        float ux, uy, uz;
        if (dim == 0)      { ux = sign; uy = a;    uz = b; }
        else if (dim == 1) { ux = a;    uy = sign; uz = b; }
        else               { ux = a;    uy = b;    uz = sign; }

        float lx = ux * s_tp[8], ly = uy * s_tp[9], lz = uz * s_tp[10];
        float yaw = s_tp[7];
        float cyw = cosf(yaw), syw = sinf(yaw);
        float rx = lx * cyw - ly * syw;
        float ry = lx * syw + ly * cyw;
        float cx = s_tp[0] + s_tp[3] * dt + 0.5f * s_tp[5] * dt * dt;
        float cy = s_tp[1] + s_tp[4] * dt + 0.5f * s_tp[6] * dt * dt;
        float wx = rx + cx, wy = ry + cy, wz = lz + s_tp[2];
        float pxr = wx - ex, pyr = wy - ey;
        float gx =  pxr * ce + pyr * se;
        float gy = -pxr * se + pyr * ce;

        const float* cal = calib + ci * 8;
        float fx = cal[0], fy = cal[1], cx0 = cal[2], cy0 = cal[3];
        float tx = cal[4], tyc = cal[5], tz = cal[6], cyaw = cal[7];
        float px = gx - tx, py = gy - tyc, pz = wz - tz;
        float cc = cosf(cyaw), sc = sinf(cyaw);
        float fwd  =  px * cc + py * sc;
        float left = -px * sc + py * cc;
        float zc = fwd, xc = -left, yc = -pz;
        float zs = fmaxf(zc, 0.1f);
        float u = fx * xc / zs + cx0;
        float v = fy * yc / zs + cy0;
        bool valid = (zc > 0.1f) && (u >= 0.f) && (u < 1.f) && (v >= 0.f) && (v < 1.f);

        if (valid) {
            float pxi = u * 159.0f;
            float pyi = v * 63.0f;
            float x0f = floorf(pxi), y0f = floorf(pyi);
            int x0 = (int)x0f, y0 = (int)y0f;
            float wxk = pxi - x0f, wyk = pyi - y0f;
            s_row[idx] = (ci * TSTEP + tt) * PLANE + y0 * WID + x0;
            s_w[idx] = make_float4((1.f - wxk) * (1.f - wyk),
                                   wxk * (1.f - wyk),
                                   (1.f - wxk) * wyk,
                                   wxk * wyk);
        } else {
            s_row[idx] = 0;
            s_w[idx]   = make_float4(0.f, 0.f, 0.f, 0.f);
        }
    }
    __syncthreads();

    // Phase B: accumulate over all taps; lane = channel -> coalesced rows.
    float acc = 0.f;
    #pragma unroll 2
    for (int i = 0; i < NTAPS; i += 2) {
        int    r0 = s_row[i],   r1 = s_row[i + 1];
        float4 w0 = s_w[i];
        float4 w1 = s_w[i + 1];
        const float* p0 = featT + (size_t)r0 * CFCH + c;
        const float* p1 = featT + (size_t)r1 * CFCH + c;
        float a00 = p0[0];
        float a01 = p0[CFCH];
        float a10 = p0[WID * CFCH];
        float a11 = p0[WID * CFCH + CFCH];
        float b00 = p1[0];
        float b01 = p1[CFCH];
        float b10 = p1[WID * CFCH];
        float b11 = p1[WID * CFCH + CFCH];
        acc = fmaf(a00, w0.x, acc);
        acc = fmaf(a01, w0.y, acc);
        acc = fmaf(a10, w0.z, acc);
        acc = fmaf(a11, w0.w, acc);
        acc = fmaf(b00, w1.x, acc);
        acc = fmaf(b01, w1.y, acc);
        acc = fmaf(b10, w1.z, acc);
        acc = fmaf(b11, w1.w, acc);
    }
    agg[m * ED + c] = acc * (1.0f / 1800.0f);
}

// ---------------- multi-head attention core ----------------
__global__ void attn_kernel(const float* __restrict__ qkv, float* __restrict__ outb)
{
    __shared__ float Ks[128 * 33];
    __shared__ float Vs[128 * 33];
    __shared__ float Qs[32 * 33];
    __shared__ float Ps[8 * 128];

    int hh = blockIdx.x;
    int qbase = blockIdx.y * 32;
    int t = threadIdx.x, lane = t & 31, w = t >> 5;

    for (int idx = t; idx < 4096; idx += 256) {
        int j = idx >> 5, d = idx & 31;
        Ks[j * 33 + d] = qkv[j * 768 + 256 + hh * 32 + d];
        Vs[j * 33 + d] = qkv[j * 768 + 512 + hh * 32 + d];
    }
    for (int idx = t; idx < 1024; idx += 256) {
        int il = idx >> 5, d = idx & 31;
        Qs[il * 33 + d] = qkv[(qbase + il) * 768 + hh * 32 + d];
    }
    __syncthreads();

    for (int r = 0; r < 4; r++) {
        int il = w * 4 + r;
        float s[4];
        #pragma unroll
        for (int jj = 0; jj < 4; jj++) {
            int j = jj * 32 + lane;
            float a = 0.f;
            #pragma unroll
            for (int d = 0; d < 32; d++)
                a = fmaf(Qs[il * 33 + d], Ks[j * 33 + d], a);
            s[jj] = a * 0.17677669529663687f;
        }
        float mx = fmaxf(fmaxf(s[0], s[1]), fmaxf(s[2], s[3]));
        for (int o = 16; o; o >>= 1) mx = fmaxf(mx, __shfl_xor_sync(0xffffffffu, mx, o));
        float ssum = 0.f;
        #pragma unroll
        for (int jj = 0; jj < 4; jj++) { s[jj] = expf(s[jj] - mx); ssum += s[jj]; }
        for (int o = 16; o; o >>= 1) ssum += __shfl_xor_sync(0xffffffffu, ssum, o);
        #pragma unroll
        for (int jj = 0; jj < 4; jj++) Ps[w * 128 + jj * 32 + lane] = s[jj];
        __syncwarp();
        float ov = 0.f;
        for (int j = 0; j < 128; j++)
            ov = fmaf(Ps[w * 128 + j], Vs[j * 33 + lane], ov);
        outb[(qbase + il) * 256 + hh * 32 + lane] = ov / ssum;
        __syncwarp();
    }
}

// ---------------- residual add + LayerNorm (in-place on q) ----------------
__global__ void resln_kernel(float* __restrict__ q, const float* __restrict__ add,
                             const float* __restrict__ g, const float* __restrict__ b)
{
    __shared__ float red[8];
    int i = blockIdx.x, t = threadIdx.x;
    float x = q[i * 256 + t] + add[i * 256 + t];

    float v = x;
    for (int o = 16; o; o >>= 1) v += __shfl_xor_sync(0xffffffffu, v, o);
    if ((t & 31) == 0) red[t >> 5] = v;
    __syncthreads();
    float total = 0.f;
    #pragma unroll
    for (int kk = 0; kk < 8; kk++) total += red[kk];
    float mean = total * (1.0f / 256.0f);
    float xm = x - mean;
    __syncthreads();

    float v2 = xm * xm;
    for (int o = 16; o; o >>= 1) v2 += __shfl_xor_sync(0xffffffffu, v2, o);
    if ((t & 31) == 0) red[t >> 5] = v2;
    __syncthreads();
    float tv = 0.f;
    #pragma unroll
    for (int kk = 0; kk < 8; kk++) tv += red[kk];
    float var = tv * (1.0f / 256.0f);

    q[i * 256 + t] = xm * rsqrtf(var + 1e-5f) * g[t] + b[t];
}

// ---------------- host orchestration ----------------
extern "C" void kernel_launch(void* const* d_in, const int* in_sizes, int n_in,
                              void* d_out, int out_size)
{
    const float* features = (const float*)d_in[0];
    const float* calib    = (const float*)d_in[1];
    const float* ego      = (const float*)d_in[2];
    const float* queries  = (const float*)d_in[3];
    const float* tw1  = (const float*)d_in[5];
    const float* tb1  = (const float*)d_in[6];
    const float* tw2  = (const float*)d_in[7];
    const float* tb2  = (const float*)d_in[8];
    const float* fmw1 = (const float*)d_in[9];
    const float* fmb1 = (const float*)d_in[10];
    const float* fmw2 = (const float*)d_in[11];
    const float* fmb2 = (const float*)d_in[12];
    const float* saiw = (const float*)d_in[13];
    const float* saib = (const float*)d_in[14];
    const float* saow = (const float*)d_in[15];
    const float* saob = (const float*)d_in[16];
    const float* caiw = (const float*)d_in[17];
    const float* caib = (const float*)d_in[18];
    const float* caow = (const float*)d_in[19];
    const float* caob = (const float*)d_in[20];
    const float* l1w  = (const float*)d_in[21];
    const float* l1b  = (const float*)d_in[22];
    const float* l2w  = (const float*)d_in[23];
    const float* l2b  = (const float*)d_in[24];
    const float* n1g  = (const float*)d_in[25];
    const float* n1b  = (const float*)d_in[26];
    const float* n2g  = (const float*)d_in[27];
    const float* n2b  = (const float*)d_in[28];
    const float* n3g  = (const float*)d_in[29];
    const float* n3b  = (const float*)d_in[30];
    float* out = (float*)d_out;

    float *q, *h, *agg, *mem, *qkv, *attno, *tmp, *tp, *featT;
    cudaGetSymbolAddress((void**)&q,     g_q);
    cudaGetSymbolAddress((void**)&h,     g_h);
    cudaGetSymbolAddress((void**)&agg,   g_agg);
    cudaGetSymbolAddress((void**)&mem,   g_mem);
    cudaGetSymbolAddress((void**)&qkv,   g_qkv);
    cudaGetSymbolAddress((void**)&attno, g_attno);
    cudaGetSymbolAddress((void**)&tmp,   g_tmp);
    cudaGetSymbolAddress((void**)&tp,    g_tp);
    cudaGetSymbolAddress((void**)&featT, g_featT);

    copy_kernel<<<(NQ * ED + 255) / 256, 256>>>(queries, q, NQ * ED);
    transpose_kernel<<<dim3(PLANE / 32, CFCH / 32, CAMSN * TSTEP), dim3(32, 8)>>>(features, featT);

    for (int li = 0; li < 6; li++) {
        gemm_kernel<1><<<dim3(4, 8), 256>>>(q, nullptr, tw1, tb1, h, 128, 512, 256);
        traj2_kernel<<<128, 352>>>(h, tw2, tb2, tp, out + li * 1408);

        sample_kernel<<<dim3(NQ, 2), 128>>>(tp, featT, calib, ego, agg);

        gemm_kernel<1><<<dim3(4, 8), 256>>>(agg, nullptr, fmw1, fmb1, h, 128, 512, 256);
        gemm_kernel<0><<<dim3(4, 4), 256>>>(h, nullptr, fmw2, fmb2, mem, 128, 256, 512);

        gemm_kernel<0><<<dim3(4, 12), 256>>>(q, nullptr, saiw + li * 768 * 256, saib + li * 768,
                                             qkv, 128, 768, 256);
        attn_kernel<<<dim3(8, 4), 256>>>(qkv, attno);
        gemm_kernel<0><<<dim3(4, 4), 256>>>(attno, nullptr, saow + li * 256 * 256, saob + li * 256,
                                            tmp, 128, 256, 256);
        resln_kernel<<<128, 256>>>(q, tmp, n1g + li * 256, n1b + li * 256);

        gemm_kernel<0><<<dim3(4, 12), 256>>>(q, mem, caiw + li * 768 * 256, caib + li * 768,
                                             qkv, 128, 768, 256);
        attn_kernel<<<dim3(8, 4), 256>>>(qkv, attno);
        gemm_kernel<0><<<dim3(4, 4), 256>>>(attno, nullptr, caow + li * 256 * 256, caob + li * 256,
                                            tmp, 128, 256, 256);
        resln_kernel<<<128, 256>>>(q, tmp, n2g + li * 256, n2b + li * 256);

        gemm_kernel<1><<<dim3(4, 8), 256>>>(q, nullptr, l1w + li * 512 * 256, l1b + li * 512,
                                            h, 128, 512, 256);
        gemm_kernel<0><<<dim3(4, 4), 256>>>(h, nullptr, l2w + li * 256 * 512, l2b + li * 256,
                                            tmp, 128, 256, 512);
        resln_kernel<<<128, 256>>>(q, tmp, n3g + li * 256, n3b + li * 256);
    }

    gemm_kernel<1><<<dim3(4, 8), 256>>>(q, nullptr, tw1, tb1, h, 128, 512, 256);
    traj2_kernel<<<128, 352>>>(h, tw2, tb2, tp, out + 6 * 1408);
}